// round 4
// baseline (speedup 1.0000x reference)
#include <cuda_runtime.h>

#define HH 256
#define WW 256
#define KK 64
#define MV 16
#define NSTEPS 64
#define VOLR 256.0f
#define DTST (1.0f/256.0f)

// Channel-interleaved template [k][z][y][x] -> float4 (4 MB, L2-resident)
__device__ float4 g_tmpl[KK * MV * MV * MV];
// Per-prim params: [0..8] R row-major, [9..11] pos (normalized), [12..14] scale, [15] pad
__device__ float g_prim[KK * 16];

__global__ void pack_kernel(const float* __restrict__ primrgba) {
    int idx = blockIdx.x * blockDim.x + threadIdx.x;
    if (idx >= KK * MV * MV * MV) return;
    int k = idx >> 12;
    int v = idx & 4095;
    const float* base = primrgba + (size_t)k * 4 * 4096 + v;
    float4 val;
    val.x = base[0];
    val.y = base[4096];
    val.z = base[8192];
    val.w = base[12288];
    g_tmpl[idx] = val;
}

__global__ void prep_kernel(const float* __restrict__ primpos,
                            const float* __restrict__ primrot,
                            const float* __restrict__ primscale) {
    int k = threadIdx.x;
    if (k >= KK) return;
    float* P = g_prim + k * 16;
#pragma unroll
    for (int i = 0; i < 9; i++) P[i] = primrot[k * 9 + i];
    P[9]  = primpos[k * 3 + 0] / VOLR;
    P[10] = primpos[k * 3 + 1] / VOLR;
    P[11] = primpos[k * 3 + 2] / VOLR;
    P[12] = primscale[k * 3 + 0];
    P[13] = primscale[k * 3 + 1];
    P[14] = primscale[k * 3 + 2];
    P[15] = 0.f;
}

// Gather 8 corners + trilinear accumulate (caller guarantees |l|<1 on all axes)
__device__ __forceinline__ void gather_tri(
    int k, float lx, float ly, float lz, float s[4])
{
    float gx = fminf((lx + 1.0f) * 7.5f, 14.99999f);
    float gy = fminf((ly + 1.0f) * 7.5f, 14.99999f);
    float gz = fminf((lz + 1.0f) * 7.5f, 14.99999f);
    int x0 = (int)gx;
    int y0 = (int)gy;
    int z0 = (int)gz;
    float fx = gx - (float)x0;
    float fy = gy - (float)y0;
    float fz = gz - (float)z0;

    const float4* T = g_tmpl + (((k * MV + z0) * MV + y0) * MV + x0);
    float4 c000 = __ldg(T + 0),   c001 = __ldg(T + 1);
    float4 c010 = __ldg(T + 16),  c011 = __ldg(T + 17);
    float4 c100 = __ldg(T + 256), c101 = __ldg(T + 257);
    float4 c110 = __ldg(T + 272), c111 = __ldg(T + 273);

    float wz0 = 1.0f - fz, wy0 = 1.0f - fy, wx0 = 1.0f - fx;
    float w000 = wz0 * wy0 * wx0, w001 = wz0 * wy0 * fx;
    float w010 = wz0 * fy * wx0,  w011 = wz0 * fy * fx;
    float w100 = fz * wy0 * wx0,  w101 = fz * wy0 * fx;
    float w110 = fz * fy * wx0,   w111 = fz * fy * fx;

    s[0] = fmaf(c000.x, w000, s[0]); s[1] = fmaf(c000.y, w000, s[1]);
    s[2] = fmaf(c000.z, w000, s[2]); s[3] = fmaf(c000.w, w000, s[3]);
    s[0] = fmaf(c001.x, w001, s[0]); s[1] = fmaf(c001.y, w001, s[1]);
    s[2] = fmaf(c001.z, w001, s[2]); s[3] = fmaf(c001.w, w001, s[3]);
    s[0] = fmaf(c010.x, w010, s[0]); s[1] = fmaf(c010.y, w010, s[1]);
    s[2] = fmaf(c010.z, w010, s[2]); s[3] = fmaf(c010.w, w010, s[3]);
    s[0] = fmaf(c011.x, w011, s[0]); s[1] = fmaf(c011.y, w011, s[1]);
    s[2] = fmaf(c011.z, w011, s[2]); s[3] = fmaf(c011.w, w011, s[3]);
    s[0] = fmaf(c100.x, w100, s[0]); s[1] = fmaf(c100.y, w100, s[1]);
    s[2] = fmaf(c100.z, w100, s[2]); s[3] = fmaf(c100.w, w100, s[3]);
    s[0] = fmaf(c101.x, w101, s[0]); s[1] = fmaf(c101.y, w101, s[1]);
    s[2] = fmaf(c101.z, w101, s[2]); s[3] = fmaf(c101.w, w101, s[3]);
    s[0] = fmaf(c110.x, w110, s[0]); s[1] = fmaf(c110.y, w110, s[1]);
    s[2] = fmaf(c110.z, w110, s[2]); s[3] = fmaf(c110.w, w110, s[3]);
    s[0] = fmaf(c111.x, w111, s[0]); s[1] = fmaf(c111.y, w111, s[1]);
    s[2] = fmaf(c111.z, w111, s[2]); s[3] = fmaf(c111.w, w111, s[3]);
}

// Compute lo/ld for one prim + exact OBB slab test.
__device__ __forceinline__ bool prep_prim(
    const float* __restrict__ P,
    float ox, float oy, float oz,
    float dx, float dy, float dz,
    float tmin, float tmax,
    float& lox, float& loy, float& loz,
    float& ldx, float& ldy, float& ldz)
{
    float rx = ox - P[9], ry = oy - P[10], rz = oz - P[11];
    lox = (rx * P[0] + ry * P[3] + rz * P[6]) * P[12];
    loy = (rx * P[1] + ry * P[4] + rz * P[7]) * P[13];
    loz = (rx * P[2] + ry * P[5] + rz * P[8]) * P[14];
    ldx = (dx * P[0] + dy * P[3] + dz * P[6]) * P[12];
    ldy = (dx * P[1] + dy * P[4] + dz * P[7]) * P[13];
    ldz = (dx * P[2] + dy * P[5] + dz * P[8]) * P[14];

    float lo3[3] = {lox, loy, loz};
    float ld3[3] = {ldx, ldy, ldz};
    float t0 = tmin, t1 = tmax;
#pragma unroll
    for (int a = 0; a < 3; a++) {
        float lo = lo3[a], ld = ld3[a];
        if (fabsf(ld) > 1e-12f) {
            float inv = 1.0f / ld;
            float ta = (-1.0f - lo) * inv;
            float tb = ( 1.0f - lo) * inv;
            t0 = fmaxf(t0, fminf(ta, tb));
            t1 = fminf(t1, fmaxf(ta, tb));
        } else if (fabsf(lo) >= 1.0f) {
            return false;
        }
    }
    return t0 <= t1;
}

// One warp per ray; lane owns steps {lane, lane+32}; lane also owns prims {lane, lane+32}.
__global__ __launch_bounds__(256) void march_kernel(
    const float* __restrict__ raypos,
    const float* __restrict__ raydir,
    const float* __restrict__ tminmax,
    float* __restrict__ out)
{
    __shared__ float sP[KK * 16];
    for (int i = threadIdx.x; i < KK * 16; i += 256) sP[i] = g_prim[i];
    __syncthreads();

    int lane = threadIdx.x & 31;
    int warpId = threadIdx.x >> 5;
    int r = blockIdx.x * 8 + warpId;  // ray index, row-major over H*W

    float ox = raypos[r * 3 + 0], oy = raypos[r * 3 + 1], oz = raypos[r * 3 + 2];
    float dx = raydir[r * 3 + 0], dy = raydir[r * 3 + 1], dz = raydir[r * 3 + 2];
    float tmin = tminmax[r * 2 + 0], tmax = tminmax[r * 2 + 1];

    // Per-lane prim prep + exact OBB cull for prims {lane, lane+32}
    float lo0x, lo0y, lo0z, ld0x, ld0y, ld0z;
    float lo1x, lo1y, lo1z, ld1x, ld1y, ld1z;
    bool a0 = prep_prim(sP + lane * 16, ox, oy, oz, dx, dy, dz, tmin, tmax,
                        lo0x, lo0y, lo0z, ld0x, ld0y, ld0z);
    bool a1 = prep_prim(sP + (lane + 32) * 16, ox, oy, oz, dx, dy, dz, tmin, tmax,
                        lo1x, lo1y, lo1z, ld1x, ld1y, ld1z);
    unsigned m0 = __ballot_sync(0xFFFFFFFFu, a0);
    unsigned m1 = __ballot_sync(0xFFFFFFFFu, a1);
    unsigned long long mask = (unsigned long long)m0 |
                              ((unsigned long long)m1 << 32);

    // Two sample points per lane
    float t0 = fmaf((float)lane + 0.5f,  DTST, tmin);
    float t1 = fmaf((float)lane + 32.5f, DTST, tmin);

    float s0[4] = {0.f, 0.f, 0.f, 0.f};
    float s1[4] = {0.f, 0.f, 0.f, 0.f};

    while (mask) {
        int k = __ffsll(mask) - 1;   // warp-uniform
        mask &= mask - 1;
        int src = k & 31;
        float Lx, Ly, Lz, Dx, Dy, Dz;
        if (k < 32) {
            Lx = __shfl_sync(0xFFFFFFFFu, lo0x, src);
            Ly = __shfl_sync(0xFFFFFFFFu, lo0y, src);
            Lz = __shfl_sync(0xFFFFFFFFu, lo0z, src);
            Dx = __shfl_sync(0xFFFFFFFFu, ld0x, src);
            Dy = __shfl_sync(0xFFFFFFFFu, ld0y, src);
            Dz = __shfl_sync(0xFFFFFFFFu, ld0z, src);
        } else {
            Lx = __shfl_sync(0xFFFFFFFFu, lo1x, src);
            Ly = __shfl_sync(0xFFFFFFFFu, lo1y, src);
            Lz = __shfl_sync(0xFFFFFFFFu, lo1z, src);
            Dx = __shfl_sync(0xFFFFFFFFu, ld1x, src);
            Dy = __shfl_sync(0xFFFFFFFFu, ld1y, src);
            Dz = __shfl_sync(0xFFFFFFFFu, ld1z, src);
        }
        // point 0
        {
            float lx = fmaf(t0, Dx, Lx);
            float ly = fmaf(t0, Dy, Ly);
            float lz = fmaf(t0, Dz, Lz);
            if (fmaxf(fmaxf(fabsf(lx), fabsf(ly)), fabsf(lz)) < 1.0f)
                gather_tri(k, lx, ly, lz, s0);
        }
        // point 1
        {
            float lx = fmaf(t1, Dx, Lx);
            float ly = fmaf(t1, Dy, Ly);
            float lz = fmaf(t1, Dz, Lz);
            if (fmaxf(fmaxf(fabsf(lx), fabsf(ly)), fabsf(lz)) < 1.0f)
                gather_tri(k, lx, ly, lz, s1);
        }
    }

    // Alpha compositing via prefix sum: alpha_i = min(1, sum_{j<=i} d_j)
    float d0 = (t0 < tmax) ? s0[3] * DTST : 0.f;
    float d1 = (t1 < tmax) ? s1[3] * DTST : 0.f;

    float c0 = d0;
#pragma unroll
    for (int off = 1; off < 32; off <<= 1) {
        float v = __shfl_up_sync(0xFFFFFFFFu, c0, off);
        if (lane >= off) c0 += v;
    }
    float tot0 = __shfl_sync(0xFFFFFFFFu, c0, 31);
    float c1 = d1;
#pragma unroll
    for (int off = 1; off < 32; off <<= 1) {
        float v = __shfl_up_sync(0xFFFFFFFFu, c1, off);
        if (lane >= off) c1 += v;
    }
    float S0 = c0;            // inclusive prefix at step lane
    float S1 = tot0 + c1;     // inclusive prefix at step lane+32
    float contrib0 = fminf(1.f, S0) - fminf(1.f, S0 - d0);
    float contrib1 = fminf(1.f, S1) - fminf(1.f, S1 - d1);

    float rgbx = s0[0] * contrib0 + s1[0] * contrib1;
    float rgby = s0[1] * contrib0 + s1[1] * contrib1;
    float rgbz = s0[2] * contrib0 + s1[2] * contrib1;

#pragma unroll
    for (int off = 16; off > 0; off >>= 1) {
        rgbx += __shfl_xor_sync(0xFFFFFFFFu, rgbx, off);
        rgby += __shfl_xor_sync(0xFFFFFFFFu, rgby, off);
        rgbz += __shfl_xor_sync(0xFFFFFFFFu, rgbz, off);
    }
    float alphaF = fminf(1.f, __shfl_sync(0xFFFFFFFFu, S1, 31));

    if (lane == 0) {
        const int HWsz = HH * WW;
        out[0 * HWsz + r] = rgbx;
        out[1 * HWsz + r] = rgby;
        out[2 * HWsz + r] = rgbz;
        out[3 * HWsz + r] = alphaF;
        out[4 * HWsz + r] = rgbx;
        out[5 * HWsz + r] = rgby;
        out[6 * HWsz + r] = rgbz;
        out[7 * HWsz + r] = alphaF;
    }
}

extern "C" void kernel_launch(void* const* d_in, const int* in_sizes, int n_in,
                              void* d_out, int out_size) {
    const float* raypos    = (const float*)d_in[0];
    const float* raydir    = (const float*)d_in[1];
    const float* tminmax   = (const float*)d_in[2];
    const float* primpos   = (const float*)d_in[3];
    const float* primrot   = (const float*)d_in[4];
    const float* primscale = (const float*)d_in[5];
    const float* primrgba  = (const float*)d_in[6];
    float* out = (float*)d_out;

    pack_kernel<<<(KK * MV * MV * MV + 255) / 256, 256>>>(primrgba);
    prep_kernel<<<1, 64>>>(primpos, primrot, primscale);
    march_kernel<<<HH * WW / 8, 256>>>(raypos, raydir, tminmax, out);
}